// round 9
// baseline (speedup 1.0000x reference)
#include <cuda_runtime.h>
#include <math.h>

// ---------------- problem constants ----------------
#define BB   2048          // graphs
#define NP   68            // nodes per graph
#define NC   8             // clusters
#define FH   128           // hidden
#define NN   (BB*NP)       // 139264 nodes
#define EE   (BB*NP*8)     // 1114112 edges
#define CSZ  (NP*NP)       // 4624
#define GT   (NN/64)       // 2176 GEMM M-tiles

typedef unsigned long long ull;

// ---------------- scratch (device globals: no allocation allowed) ----------------
__device__ float g_C [BB*CSZ];     // per-graph dst x src count matrix
__device__ float g_P [(size_t)NN*FH];   // H @ W_rel
__device__ float g_Rb[(size_t)NN*FH];   // H @ W_root + b
__device__ float g_HA[(size_t)NN*FH];
__device__ float g_HB[(size_t)NN*FH];
__device__ int   g_is64;

// ---------------- f32x2 packed helpers ----------------
__device__ __forceinline__ void fma2(ull& d, ull a, ull b){
    asm("fma.rn.f32x2 %0, %1, %2, %0;" : "+l"(d) : "l"(a), "l"(b));
}
__device__ __forceinline__ ull dup2(float x){
    ull r; asm("mov.b64 %0, {%1, %1};" : "=l"(r) : "f"(x)); return r;
}
__device__ __forceinline__ float2 unpack2(ull v){
    float2 f; asm("mov.b64 {%0, %1}, %2;" : "=f"(f.x), "=f"(f.y) : "l"(v)); return f;
}

// ---------------- edge dtype detect: int64 has zero high words ----------------
__global__ void k_detect(const int* __restrict__ ei){
    __shared__ int anynz;
    int t = threadIdx.x;
    if (t == 0) anynz = 0;
    __syncthreads();
    if (ei[2*t + 1] != 0) atomicOr(&anynz, 1);
    __syncthreads();
    if (t == 0) g_is64 = (anynz == 0) ? 1 : 0;
}

__global__ void k_zeroC(){
    size_t idx = (size_t)blockIdx.x*blockDim.x + threadIdx.x;
    size_t tot = (size_t)BB*CSZ;
    size_t str = (size_t)gridDim.x*blockDim.x;
    for (size_t i = idx; i < tot; i += str) g_C[i] = 0.0f;
}

// build C[g][dst_local][src_local] += 1 (exact integer floats)
__global__ void k_edges(const int* __restrict__ ei){
    const int is64 = g_is64;
    int e = blockIdx.x*blockDim.x + threadIdx.x;
    if (e >= EE) return;
    int s, d;
    if (is64){ s = ei[2*e]; d = ei[2*(EE + e)]; }
    else     { s = ei[e];   d = ei[EE + e];    }
    int gd = d / NP;  int ld = d - gd*NP;
    int gs = s / NP;  int ls = s - gs*NP;     // gs == gd by construction
    (void)gs;
    atomicAdd(&g_C[(size_t)gd*CSZ + ld*NP + ls], 1.0f);
}

// ---------------- layer 1 (F_IN = 2): HA = relu(C@x@Wrel + x@Wroot + b) ----------------
__global__ void k_layer1(const float* __restrict__ x,
                         const float* __restrict__ Wrel, const float* __restrict__ Wroot,
                         const float* __restrict__ b){
    __shared__ float xs[NP*2], ax[NP*2], wr[2*FH], wo[2*FH], bs[FH];
    const int g = blockIdx.x, t = threadIdx.x;
    if (t < NP*2) xs[t] = x[(size_t)g*NP*2 + t];
    if (t < FH){
        wr[t] = Wrel[t];  wr[FH+t] = Wrel[FH+t];
        wo[t] = Wroot[t]; wo[FH+t] = Wroot[FH+t];
        bs[t] = b[t];
    }
    __syncthreads();
    if (t < NP*2){
        int n = t >> 1, d = t & 1;
        const float* crow = g_C + (size_t)g*CSZ + n*NP;
        float sv = 0.0f;
        for (int j = 0; j < NP; j++) sv += crow[j] * xs[j*2 + d];
        ax[t] = sv;                       // ax[n*2+d]
    }
    __syncthreads();
    for (int idx = t; idx < NP*FH; idx += blockDim.x){
        int n = idx >> 7, f = idx & 127;
        float v = ax[n*2]*wr[f] + ax[n*2+1]*wr[FH+f]
                + xs[n*2]*wo[f] + xs[n*2+1]*wo[FH+f] + bs[f];
        g_HA[(size_t)g*NP*FH + idx] = fmaxf(v, 0.0f);
    }
}

// ---------------- dual GEMM: P = H@Wrel, Rb = H@Wroot + b ----------------
// K-paired f32x2: lanes of the pair carry even/odd-k partial sums, folded in epilogue.
#define WT_STRIDE 130           // Wt[256][130] transposed (f-major, k contiguous)
#define AS_STRIDE 132           // As[64][132]
#define GEMM_SMEM ((256*WT_STRIDE + 64*AS_STRIDE + 128)*4)

__global__ void __launch_bounds__(256) k_gemm(int layer,
                         const float* __restrict__ Wrel, const float* __restrict__ Wroot,
                         const float* __restrict__ bias){
    extern __shared__ float sm[];
    float* Wt = sm;                         // 256*130
    float* As = sm + 256*WT_STRIDE;         // 64*132
    float* bs = As + 64*AS_STRIDE;          // 128
    const float* __restrict__ Hin = (layer == 2) ? g_HA : g_HB;
    const int t = threadIdx.x;

    for (int i = t; i < 256*128; i += 256){
        int f = i >> 7, k = i & 127;
        float v = (f < 128) ? Wrel[k*128 + f] : Wroot[k*128 + (f-128)];
        Wt[f*WT_STRIDE + k] = v;
    }
    if (t < 128) bs[t] = bias[t];
    __syncthreads();

    const int r = t >> 5;      // 0..7  -> 8 rows each
    const int c = t & 31;      // 0..31 -> cols f = c + 32*j

    for (int tile = blockIdx.x; tile < GT; tile += gridDim.x){
        #pragma unroll
        for (int i = 0; i < 8; i++){
            int lin = t + 256*i;                 // 0..2047
            int row = lin >> 5;
            int kc  = (lin & 31) << 2;
            float4 v = *(const float4*)(Hin + (size_t)(tile*64 + row)*128 + kc);
            *(float4*)(As + row*AS_STRIDE + kc) = v;
        }
        __syncthreads();

        ull acc[8][8];
        #pragma unroll
        for (int i = 0; i < 8; i++)
            #pragma unroll
            for (int j = 0; j < 8; j++) acc[i][j] = 0ULL;

        #pragma unroll 4
        for (int k = 0; k < 128; k += 2){
            ull a[8], b[8];
            #pragma unroll
            for (int i = 0; i < 8; i++)
                a[i] = *(const ull*)(As + (r*8 + i)*AS_STRIDE + k);
            #pragma unroll
            for (int j = 0; j < 8; j++)
                b[j] = *(const ull*)(Wt + (c + 32*j)*WT_STRIDE + k);
            #pragma unroll
            for (int i = 0; i < 8; i++)
                #pragma unroll
                for (int j = 0; j < 8; j++)
                    fma2(acc[i][j], a[i], b[j]);
        }

        #pragma unroll
        for (int i = 0; i < 8; i++){
            size_t node = (size_t)tile*64 + r*8 + i;
            #pragma unroll
            for (int j = 0; j < 8; j++){
                float2 p = unpack2(acc[i][j]);
                float v = p.x + p.y;
                int f = c + 32*j;
                if (f < 128) g_P [node*128 + f]       = v;
                else         g_Rb[node*128 + (f-128)] = v + bs[f-128];
            }
        }
        __syncthreads();
    }
}

// ---------------- conv-apply: H_out = relu(C_g @ P_g + Rb_g) ----------------
#define CONV_SMEM ((NP*FH + CSZ)*4)
__global__ void k_conv(int layer){
    extern __shared__ float sm[];
    float* Ps = sm;            // 68*128
    float* Cs = sm + NP*FH;    // 68*68
    const int g = blockIdx.x, t = threadIdx.x;
    float* __restrict__ Hout = (layer == 2) ? g_HB : g_HA;

    const float* Pg = g_P + (size_t)g*NP*FH;
    for (int i = t; i < NP*FH; i += 544) Ps[i] = Pg[i];
    const float* Cg = g_C + (size_t)g*CSZ;
    for (int i = t; i < CSZ; i += 544) Cs[i] = Cg[i];
    __syncthreads();

    const int n  = t >> 3;     // 0..67
    const int cg = t & 7;      // 0..7 -> pair cols cg + 8u (bank-friendly stride)
    const float* rb = g_Rb + ((size_t)g*NP + n)*FH;
    ull acc[8];
    #pragma unroll
    for (int u = 0; u < 8; u++) acc[u] = *(const ull*)(rb + 2*(cg + 8*u));

    const float* crow = Cs + n*NP;
    #pragma unroll 4
    for (int j = 0; j < NP; j++){
        ull cc = dup2(crow[j]);
        const float* pr = Ps + j*FH;
        #pragma unroll
        for (int u = 0; u < 8; u++){
            ull pv = *(const ull*)(pr + 2*(cg + 8*u));
            fma2(acc[u], cc, pv);
        }
    }
    float* ho = Hout + ((size_t)g*NP + n)*FH;
    #pragma unroll
    for (int u = 0; u < 8; u++){
        float2 v = unpack2(acc[u]);
        v.x = fmaxf(v.x, 0.0f); v.y = fmaxf(v.y, 0.0f);
        *(float2*)(ho + 2*(cg + 8*u)) = v;
    }
}

// ---------------- pool: softmax(s) einsum, maxpool(1,8), fc ----------------
__global__ void k_pool(const float* __restrict__ s_in,
                       const float* __restrict__ fcw, const float* __restrict__ fcb,
                       float* __restrict__ out){
    __shared__ float ssm[NP*NC];
    __shared__ float xp[NC*FH];
    __shared__ float red[128];
    const int g = blockIdx.x, t = threadIdx.x;

    if (t < NP){
        float v[NC]; float m = -1e30f;
        #pragma unroll
        for (int k = 0; k < NC; k++){ v[k] = s_in[((size_t)g*NP + t)*NC + k]; m = fmaxf(m, v[k]); }
        float sum = 0.0f;
        #pragma unroll
        for (int k = 0; k < NC; k++){ v[k] = expf(v[k]-m); sum += v[k]; }
        float inv = 1.0f/sum;
        #pragma unroll
        for (int k = 0; k < NC; k++) ssm[t*NC+k] = v[k]*inv;
    }
    __syncthreads();

    const float* Hg = g_HA + (size_t)g*NP*FH;
    for (int idx = t; idx < NC*FH; idx += 256){
        int c = idx >> 7, f = idx & 127;
        float acc = 0.0f;
        for (int n = 0; n < NP; n++) acc += ssm[n*NC+c] * Hg[n*FH + f];
        xp[c*FH + f] = acc;
    }
    __syncthreads();

    if (t < 128){
        int c = t >> 4, j = t & 15;
        float m = xp[c*FH + j*8];
        #pragma unroll
        for (int u = 1; u < 8; u++) m = fmaxf(m, xp[c*FH + j*8 + u]);
        red[t] = m * fcw[t];
    }
    __syncthreads();
    if (t < 64) red[t] += red[t+64];
    __syncthreads();
    if (t < 32){
        float v = red[t] + red[t+32];
        #pragma unroll
        for (int o = 16; o; o >>= 1) v += __shfl_down_sync(0xffffffffu, v, o);
        if (t == 0) out[g] = v + fcb[0];
    }
}

// ---------------- launch ----------------
extern "C" void kernel_launch(void* const* d_in, const int* in_sizes, int n_in,
                              void* d_out, int out_size){
    const float* x    = (const float*)d_in[0];
    const int*   ei   = (const int*)  d_in[1];
    // d_in[2] = adj : unused (pool losses are discarded in reference)
    const float* s_in = (const float*)d_in[3];
    const float* Wro1 = (const float*)d_in[4];
    const float* Wre1 = (const float*)d_in[5];
    const float* b1   = (const float*)d_in[6];
    const float* Wro2 = (const float*)d_in[7];
    const float* Wre2 = (const float*)d_in[8];
    const float* b2   = (const float*)d_in[9];
    const float* Wro3 = (const float*)d_in[10];
    const float* Wre3 = (const float*)d_in[11];
    const float* b3   = (const float*)d_in[12];
    const float* fcw  = (const float*)d_in[13];
    const float* fcb  = (const float*)d_in[14];
    float* out = (float*)d_out;
    (void)in_sizes; (void)n_in; (void)out_size;

    cudaFuncSetAttribute(k_gemm, cudaFuncAttributeMaxDynamicSharedMemorySize, GEMM_SMEM);
    cudaFuncSetAttribute(k_conv, cudaFuncAttributeMaxDynamicSharedMemorySize, CONV_SMEM);

    k_detect<<<1, 256>>>(ei);
    k_zeroC<<<4096, 256>>>();
    k_edges<<<EE/256, 256>>>(ei);

    k_layer1<<<BB, 256>>>(x, Wre1, Wro1, b1);                 // -> g_HA

    k_gemm<<<296, 256, GEMM_SMEM>>>(2, Wre2, Wro2, b2);       // g_HA -> g_P, g_Rb
    k_conv<<<BB, 544, CONV_SMEM>>>(2);                        // -> g_HB

    k_gemm<<<296, 256, GEMM_SMEM>>>(3, Wre3, Wro3, b3);       // g_HB -> g_P, g_Rb
    k_conv<<<BB, 544, CONV_SMEM>>>(3);                        // -> g_HA

    k_pool<<<BB, 256>>>(s_in, fcw, fcb, out);
}